// round 7
// baseline (speedup 1.0000x reference)
#include <cuda_runtime.h>
#include <cuda_bf16.h>

// ProjectBEV: input (B=16, H=64, W=2048, CK=3, 2) float32.
// Output element order is (B, CK, H, W); N = B*CK*H*W = 6,291,456.
// Output (float32, concatenated):
//   [0   , 6N )  presence_indices rows [b, qx, qy, c, h, w]
//   [6N  , 7N )  presence_vals (all 1)
//   [7N  , 21N)  position_indices rows [b, qx, qy, c, h, w, d], d=0,1
//   [21N , 23N)  position_vals [sx, sy]
// sx = 2x+1, sy = 2y+81, qx = trunc(sx), qy = trunc(sy).
//
// R7 mapping: thread t owns (b, h, w0=2*w2) and ALL 3 channels (6 elements).
// Input float offset for (b,h,w0,c=0) is ((b*64+h)*2048 + w0)*6 = 12*t,
// so the input is read as 3 perfectly-linear float4 per thread (each byte once).

#define W_DIM 2048
#define H_DIM 64
#define CK_DIM 3

__global__ __launch_bounds__(256)
void project_bev_kernel(const float4* __restrict__ in,
                        float* __restrict__ out,
                        long N)
{
    const long T = N / 6;                      // B*H*W/2 threads
    const long t = (long)blockIdx.x * blockDim.x + threadIdx.x;
    if (t >= T) return;

    // t -> (b, h, w2); W/2 = 1024, H = 64
    const int w2 = (int)(t & 1023);
    const int h  = (int)((t >> 10) & 63);
    const int b  = (int)(t >> 16);
    const int w0 = w2 << 1;

    // 3 independent linear loads (front-batched, MLP=3)
    const float4 f0 = __ldcs(in + 3 * t + 0);  // w0:c0(x,y)  w0:c1(x,y)
    const float4 f1 = __ldcs(in + 3 * t + 1);  // w0:c2(x,y)  w1:c0(x,y)
    const float4 f2 = __ldcs(in + 3 * t + 2);  // w1:c1(x,y)  w1:c2(x,y)

    // per-channel (x,y) for the two w's
    float x0[3], y0[3], x1[3], y1[3];
    x0[0] = f0.x; y0[0] = f0.y;   x1[0] = f1.z; y1[0] = f1.w;
    x0[1] = f0.z; y0[1] = f0.w;   x1[1] = f2.x; y1[1] = f2.y;
    x0[2] = f1.x; y0[2] = f1.y;   x1[2] = f2.z; y1[2] = f2.w;

    const float bf  = (float)b;
    const float hf  = (float)h;
    const float wf0 = (float)w0;
    const float wf1 = (float)(w0 + 1);

#pragma unroll
    for (int c = 0; c < CK_DIM; c++) {
        // flattened output element index (even)
        const long n = (((long)(b * CK_DIM + c) * H_DIM + h) << 11) + w0;
        const float cf = (float)c;

        const float sx0 = x0[c] * 2.0f + 1.0f;
        const float sy0 = y0[c] * 2.0f + 81.0f;
        const float sx1 = x1[c] * 2.0f + 1.0f;
        const float sy1 = y1[c] * 2.0f + 81.0f;
        const float qx0 = (float)(int)sx0;     // positive -> trunc == astype(int64)
        const float qy0 = (float)(int)sy0;
        const float qx1 = (float)(int)sx1;
        const float qy1 = (float)(int)sy1;

        // presence_indices: 12 floats at out[6*n] (n even -> 16B aligned)
        {
            float4* p = (float4*)(out + 6 * n);
            __stcs(p + 0, make_float4(bf,  qx0, qy0, cf ));
            __stcs(p + 1, make_float4(hf,  wf0, bf,  qx1));
            __stcs(p + 2, make_float4(qy1, cf,  hf,  wf1));
        }

        // presence_vals: 2 floats at out[6N + n]
        __stcs((float2*)(out + 6 * N + n), make_float2(1.0f, 1.0f));

        // position_indices: 28 floats at out[7N + 14*n] (16B aligned)
        {
            float4* p = (float4*)(out + 7 * N + 14 * n);
            __stcs(p + 0, make_float4(bf,  qx0, qy0, cf ));
            __stcs(p + 1, make_float4(hf,  wf0, 0.0f, bf ));
            __stcs(p + 2, make_float4(qx0, qy0, cf,  hf ));
            __stcs(p + 3, make_float4(wf0, 1.0f, bf,  qx1));
            __stcs(p + 4, make_float4(qy1, cf,  hf,  wf1));
            __stcs(p + 5, make_float4(0.0f, bf, qx1, qy1));
            __stcs(p + 6, make_float4(cf,  hf,  wf1, 1.0f));
        }

        // position_vals: 4 floats at out[21N + 2*n] (n even -> 16B aligned)
        __stcs((float4*)(out + 21 * N + 2 * n),
               make_float4(sx0, sy0, sx1, sy1));
    }
}

extern "C" void kernel_launch(void* const* d_in, const int* in_sizes, int n_in,
                              void* d_out, int out_size)
{
    const float4* in = (const float4*)d_in[0];
    float* out = (float*)d_out;

    const long N = (long)in_sizes[0] / 2;      // number of (x,y) points
    const long T = N / 6;                      // threads

    const int threads = 256;
    const int blocks = (int)((T + threads - 1) / threads);
    project_bev_kernel<<<blocks, threads>>>(in, out, N);
}

// round 8
// speedup vs baseline: 1.3157x; 1.3157x over previous
#include <cuda_runtime.h>
#include <cuda_bf16.h>

// ProjectBEV: input (B=16, H=64, W=2048, CK=3, 2) float32.
// Flattened element order (B, CK, H, W); N = 6,291,456.
// Output (float32, concatenated):
//   [0   , 6N )  presence_indices rows [b, qx, qy, c, h, w]
//   [6N  , 7N )  presence_vals (all 1)
//   [7N  , 21N)  position_indices rows [b, qx, qy, c, h, w, d], d=0,1
//   [21N , 23N)  position_vals [sx, sy]
// sx = 2x+1, sy = 2y+81, qx = trunc(sx), qy = trunc(sy).
//
// R8: region-split blocks. blockIdx.x & 3 selects output region; blockIdx.x >> 2
// selects a 512-element span. Adjacent blocks cover the same span, so the 3
// region-blocks that read input share its L2 lines. Short store chains per
// thread + 3.3x thread count vs R6 -> more memory-level parallelism in flight.

__global__ __launch_bounds__(256)
void project_bev_kernel(const float* __restrict__ in,
                        float* __restrict__ out,
                        long N)
{
    const int  region = (int)(blockIdx.x & 3);
    const long span   = (long)(blockIdx.x >> 2);

    // ---- region 3: presence_vals — pure constant fill, no loads ----
    if (region == 3) {
        if (threadIdx.x < 128) {
            float4* p = (float4*)(out + 6 * N + span * 512) + threadIdx.x;
            __stcs(p, make_float4(1.0f, 1.0f, 1.0f, 1.0f));
        }
        return;
    }

    // pair index: this thread owns elements (2t, 2t+1)
    const long t  = span * 256 + threadIdx.x;
    const long i0 = t << 1;

    // decode (B, CK, H, W) indices; w0 even so both elems share b,c,h
    const int w0 = (int)(i0 & 2047);
    const int h  = (int)((i0 >> 11) & 63);
    const int hi = (int)(i0 >> 17);          // b*3 + c
    const int b  = hi / 3;
    const int c  = hi - 3 * b;

    // input offset in float2 units: (((b*64 + h)*2048 + w0)*3 + c)
    const long in_off = ((long)((b * 64 + h) * 2048 + w0)) * 3 + c;
    const float2 p0 = __ldg(((const float2*)in) + in_off);      // default caching:
    const float2 p1 = __ldg(((const float2*)in) + in_off + 3);  // reused across regions

    const float sx0 = p0.x * 2.0f + 1.0f;
    const float sy0 = p0.y * 2.0f + 81.0f;
    const float sx1 = p1.x * 2.0f + 1.0f;
    const float sy1 = p1.y * 2.0f + 81.0f;

    if (region == 2) {
        // ---- position_vals: 1 STG.128 at out[21N + 4t] ----
        __stcs((float4*)(out + 21 * N + 4 * t),
               make_float4(sx0, sy0, sx1, sy1));
        return;
    }

    const float qx0 = (float)(int)sx0;   // positive -> trunc == astype(int64)
    const float qy0 = (float)(int)sy0;
    const float qx1 = (float)(int)sx1;
    const float qy1 = (float)(int)sy1;
    const float bf  = (float)b;
    const float cf  = (float)c;
    const float hf  = (float)h;
    const float wf0 = (float)w0;
    const float wf1 = (float)(w0 + 1);

    if (region == 0) {
        // ---- presence_indices: 3 STG.128 at out[12t] ----
        float4* p = (float4*)(out + 12 * t);
        __stcs(p + 0, make_float4(bf,  qx0, qy0, cf ));
        __stcs(p + 1, make_float4(hf,  wf0, bf,  qx1));
        __stcs(p + 2, make_float4(qy1, cf,  hf,  wf1));
    } else {
        // ---- position_indices: 7 STG.128 at out[7N + 28t] ----
        float4* p = (float4*)(out + 7 * N + 28 * t);
        __stcs(p + 0, make_float4(bf,   qx0, qy0,  cf ));
        __stcs(p + 1, make_float4(hf,   wf0, 0.0f, bf ));
        __stcs(p + 2, make_float4(qx0,  qy0, cf,   hf ));
        __stcs(p + 3, make_float4(wf0, 1.0f, bf,   qx1));
        __stcs(p + 4, make_float4(qy1,  cf,  hf,   wf1));
        __stcs(p + 5, make_float4(0.0f, bf,  qx1,  qy1));
        __stcs(p + 6, make_float4(cf,   hf,  wf1, 1.0f));
    }
}

extern "C" void kernel_launch(void* const* d_in, const int* in_sizes, int n_in,
                              void* d_out, int out_size)
{
    const float* in = (const float*)d_in[0];
    float* out = (float*)d_out;

    const long N     = (long)in_sizes[0] / 2;   // number of (x,y) points
    const long spans = N / 512;                 // 512 elements per span (exact)
    const int  blocks = (int)(spans * 4);       // 4 region-blocks per span

    project_bev_kernel<<<blocks, 256>>>(in, out, N);
}